// round 6
// baseline (speedup 1.0000x reference)
#include <cuda_runtime.h>
#include <cuda_bf16.h>

#define T_IN   4096
#define T2     8192
#define C_CH   512
#define B_N    16
#define THREADS 128
#define TOUT    16
#define NOUT_BLK 2048
#define SEGS   2
#define SXN    2064    // staged x: raw [start-8, start+2055], edge-clamped

// kaiser_sinc_filter1d(0.25, 0.3, 12) — precomputed, symmetric (h[k]==h[11-k]).
#define H0 0.00202897f
#define H1 0.00938893f
#define H2 (-0.02554347f)
#define H3 (-0.05765742f)
#define H4 0.12857272f
#define H5 0.44321013f

// Up-sampling polyphase taps (2x gain folded in):
// even u=2s:   y = sum_m UE[m]*x[s+m-3],  UE[m] = 2*h[11-2m]
// odd  u=2s+1: y = sum_m UO[m]*x[s+m-2],  UO[m] = 2*h[10-2m]
__device__ constexpr float UE[6] = { 2.0f*H0, 2.0f*H2, 2.0f*H4, 2.0f*H5, 2.0f*H3, 2.0f*H1 };
__device__ constexpr float UO[6] = { 2.0f*H1, 2.0f*H3, 2.0f*H5, 2.0f*H4, 2.0f*H2, 2.0f*H0 };
// Down-sampling taps
__device__ constexpr float DD[12] = { H0, H1, H2, H3, H4, H5, H5, H4, H3, H2, H1, H0 };

__global__ __launch_bounds__(THREADS)
void aa_act_kernel(const float* __restrict__ x,
                   const float* __restrict__ alpha,
                   const float* __restrict__ beta,
                   const float* __restrict__ uf,   // unused: taps are immediates
                   const float* __restrict__ df,   // unused
                   float* __restrict__ out)
{
    __shared__ __align__(16) float sx[SXN];

    const int bx    = blockIdx.x;
    const int r     = bx >> 1;        // row = b*C + c
    const int seg   = bx & 1;
    const int start = seg << 11;      // 0 or 2048
    const int c     = r & (C_CH - 1);
    const int tid   = threadIdx.x;
    const int base  = start - 8;      // raw x index of sx[0]

    const float* xrow = x + (size_t)r * T_IN;
    float* orow       = out + (size_t)r * T_IN;

    // ---- Vectorized staging: sx[i] = x[clamp(base+i)] ----
    float4* dst4 = reinterpret_cast<float4*>(sx);
    if (seg == 0) {
        // sx[0..7] = x[0] (clamp), sx[8..2063] = x[0..2055]
        const float4* s4p = reinterpret_cast<const float4*>(xrow);
#pragma unroll
        for (int it = 0; it < 5; ++it) {
            int i = tid + it * THREADS;
            if (i < 514) dst4[i + 2] = __ldg(s4p + i);
        }
        if (tid < 8) sx[tid] = __ldg(xrow);
    } else {
        // sx[0..2055] = x[2040..4095], sx[2056..2063] = x[4095] (clamp)
        const float4* s4p = reinterpret_cast<const float4*>(xrow + 2040);
#pragma unroll
        for (int it = 0; it < 5; ++it) {
            int i = tid + it * THREADS;
            if (i < 514) dst4[i] = __ldg(s4p + i);
        }
        if (tid < 8) sx[2056 + tid] = __ldg(xrow + (T_IN - 1));
    }

    const float ea   = __expf(__ldg(alpha + c));
    const float ieb  = 1.0f / (__expf(__ldg(beta + c)) + 1e-9f);
    const float ea2  = 2.0f * ea;      // cos(2*ea*y)
    const float ieb2 = 0.5f * ieb;     // snake: y + ieb2 - ieb2*cos(2*ea*y)
    const float nieb2 = -ieb2;

    __syncthreads();

    const int t0 = start + tid * TOUT;
    // fast iff y window [2t0-5, 2t0+36] needs no clamping
    const bool fast_ok = (t0 >= 3) && (t0 <= 4077);

    if (fast_ok) {
        // x window raw [t0-8, t0+23] -> rx[0..31]; float4 index 4*tid (aligned)
        float rx[32];
        const float4* s4 = reinterpret_cast<const float4*>(sx);
        const int q4 = 4 * tid;
#pragma unroll
        for (int i = 0; i < 8; i++) {
            float4 v = s4[q4 + i];
            rx[4 * i + 0] = v.x; rx[4 * i + 1] = v.y;
            rx[4 * i + 2] = v.z; rx[4 * i + 3] = v.w;
        }

        float acc[TOUT];
#pragma unroll
        for (int q = 0; q < TOUT; q++) acc[q] = ieb2;   // folded snake constant

        // y index u = 2*t0 - 5 + j, j = 0..41; step i handles j=2i (u odd), j=2i+1 (u even)
#pragma unroll
        for (int i = 0; i <= 20; ++i) {
            float yo = UO[0] * rx[i + 3];
            float ye = UE[0] * rx[i + 3];
#pragma unroll
            for (int m = 1; m < 6; ++m) {
                yo = fmaf(UO[m], rx[i + 3 + m], yo);
                ye = fmaf(UE[m], rx[i + 3 + m], ye);
            }
            // snake (3 ops): w = y - ieb2*cos(2*ea*y)   (constant folded into acc init)
            float co = __cosf(yo * ea2);
            float ce = __cosf(ye * ea2);
            yo = fmaf(nieb2, co, yo);
            ye = fmaf(nieb2, ce, ye);
            // scatter: y[j] feeds acc[q] with tap k = j - 2q in [0,12)
#pragma unroll
            for (int q = 0; q < TOUT; ++q) {
                const int k0 = 2 * i - 2 * q;       // yo (j = 2i)
                if (k0 >= 0 && k0 < 12) acc[q] = fmaf(DD[k0], yo, acc[q]);
                const int k1 = 2 * i + 1 - 2 * q;   // ye (j = 2i+1)
                if (k1 >= 0 && k1 < 12) acc[q] = fmaf(DD[k1], ye, acc[q]);
            }
        }

#pragma unroll
        for (int v = 0; v < 4; ++v)
            *reinterpret_cast<float4*>(orow + t0 + 4 * v) =
                make_float4(acc[4 * v], acc[4 * v + 1], acc[4 * v + 2], acc[4 * v + 3]);
    } else {
        // Edge path (t0==0 or t0==4080): y-index clamping, same math.
        float acc[TOUT];
#pragma unroll
        for (int q = 0; q < TOUT; q++) acc[q] = ieb2;

#pragma unroll 1
        for (int j = 0; j < 42; ++j) {
            int u = 2 * t0 - 5 + j;
            u = u < 0 ? 0 : (u > T2 - 1 ? T2 - 1 : u);
            const int s   = u >> 1;
            const int idx = s - base;
            float yv;
            if (u & 1) {
                yv = UO[0] * sx[idx - 2];
#pragma unroll
                for (int m = 1; m < 6; ++m) yv = fmaf(UO[m], sx[idx + m - 2], yv);
            } else {
                yv = UE[0] * sx[idx - 3];
#pragma unroll
                for (int m = 1; m < 6; ++m) yv = fmaf(UE[m], sx[idx + m - 3], yv);
            }
            float cc = __cosf(yv * ea2);
            yv = fmaf(nieb2, cc, yv);
#pragma unroll
            for (int q = 0; q < TOUT; ++q) {
                const int k = j - 2 * q;
                if (k >= 0 && k < 12) acc[q] = fmaf(DD[k], yv, acc[q]);
            }
        }
#pragma unroll
        for (int q = 0; q < TOUT; q++) orow[t0 + q] = acc[q];
    }
}

extern "C" void kernel_launch(void* const* d_in, const int* in_sizes, int n_in,
                              void* d_out, int out_size) {
    const float* x     = (const float*)d_in[0];
    const float* alpha = (const float*)d_in[1];
    const float* beta  = (const float*)d_in[2];
    const float* uf    = (const float*)d_in[3];
    const float* df    = (const float*)d_in[4];
    float* out = (float*)d_out;

    dim3 grid(B_N * C_CH * SEGS);   // 16384 blocks
    aa_act_kernel<<<grid, THREADS>>>(x, alpha, beta, uf, df, out);
}

// round 7
// speedup vs baseline: 1.8218x; 1.8218x over previous
#include <cuda_runtime.h>
#include <cuda_bf16.h>

#define T_IN   4096
#define T2     8192
#define C_CH   512
#define B_N    16
#define THREADS 128
#define TOUT    8
#define NOUT_BLK 1024
#define SEGS   4
#define SXN    1040    // staged x: raw [start-8, start+1031], edge-clamped

// kaiser_sinc_filter1d(0.25, 0.3, 12) — precomputed, symmetric (h[k]==h[11-k]).
#define H0 0.00202897f
#define H1 0.00938893f
#define H2 (-0.02554347f)
#define H3 (-0.05765742f)
#define H4 0.12857272f
#define H5 0.44321013f

// Up-sampling polyphase taps (2x gain folded in):
// even u=2s:   y = sum_m UE[m]*x[s+m-3],  UE[m] = 2*h[11-2m]
// odd  u=2s+1: y = sum_m UO[m]*x[s+m-2],  UO[m] = 2*h[10-2m]
__device__ constexpr float UE[6] = { 2.0f*H0, 2.0f*H2, 2.0f*H4, 2.0f*H5, 2.0f*H3, 2.0f*H1 };
__device__ constexpr float UO[6] = { 2.0f*H1, 2.0f*H3, 2.0f*H5, 2.0f*H4, 2.0f*H2, 2.0f*H0 };
// Down-sampling taps
__device__ constexpr float DD[12] = { H0, H1, H2, H3, H4, H5, H5, H4, H3, H2, H1, H0 };

__global__ __launch_bounds__(THREADS, 6)   // allow ~85 regs: keep rx/acc resident
void aa_act_kernel(const float* __restrict__ x,
                   const float* __restrict__ alpha,
                   const float* __restrict__ beta,
                   const float* __restrict__ uf,   // unused: taps are immediates
                   const float* __restrict__ df,   // unused
                   float* __restrict__ out)
{
    __shared__ __align__(16) float sx[SXN];

    const int bx    = blockIdx.x;
    const int r     = bx >> 2;        // row = b*C + c
    const int seg   = bx & 3;
    const int start = seg << 10;
    const int c     = r & (C_CH - 1);
    const int tid   = threadIdx.x;
    const int base  = start - 8;      // raw x index of sx[0]

    const float* xrow = x + (size_t)r * T_IN;
    float* orow       = out + (size_t)r * T_IN;

    // ---- Vectorized staging: sx[i] = x[clamp(base+i)] ----
    float4* dst4 = reinterpret_cast<float4*>(sx);
    if (seg == 0) {
        // sx[0..7] = x[0] (left clamp); sx[8..1039] = x[0..1031]
        const float4* s4p = reinterpret_cast<const float4*>(xrow);
#pragma unroll
        for (int it = 0; it < 3; ++it) {
            int i = tid + it * THREADS;
            if (i < 258) dst4[i + 2] = __ldg(s4p + i);
        }
        if (tid < 8) sx[tid] = __ldg(xrow);
    } else if (seg == 3) {
        // sx[0..1031] = x[3064..4095]; sx[1032..1039] = x[4095] (right clamp)
        const float4* s4p = reinterpret_cast<const float4*>(xrow + 3064);
#pragma unroll
        for (int it = 0; it < 3; ++it) {
            int i = tid + it * THREADS;
            if (i < 258) dst4[i] = __ldg(s4p + i);
        }
        if (tid < 8) sx[1032 + tid] = __ldg(xrow + (T_IN - 1));
    } else {
        // fully interior: sx[0..1039] = x[start-8 .. start+1031]
        const float4* s4p = reinterpret_cast<const float4*>(xrow + (start - 8));
#pragma unroll
        for (int it = 0; it < 3; ++it) {
            int i = tid + it * THREADS;
            if (i < 260) dst4[i] = __ldg(s4p + i);
        }
    }

    const float ea    = __expf(__ldg(alpha + c));
    const float ieb   = 1.0f / (__expf(__ldg(beta + c)) + 1e-9f);
    const float ea2   = 2.0f * ea;     // cos(2*ea*y)
    const float ieb2  = 0.5f * ieb;    // snake: y + ieb2 - ieb2*cos(2*ea*y)
    const float nieb2 = -ieb2;

    __syncthreads();

    const int t0 = start + tid * TOUT;
    // fast iff y window [2t0-5, 2t0+20] needs no clamping
    const bool fast_ok = (t0 >= 3) && (t0 <= 4085);

    if (fast_ok) {
        // x window raw [t0-8, t0+15] -> rx[0..23]; float4 index 2*tid (aligned)
        float rx[24];
        const float4* s4 = reinterpret_cast<const float4*>(sx);
        const int q4 = 2 * tid;
#pragma unroll
        for (int i = 0; i < 6; i++) {
            float4 v = s4[q4 + i];
            rx[4 * i + 0] = v.x; rx[4 * i + 1] = v.y;
            rx[4 * i + 2] = v.z; rx[4 * i + 3] = v.w;
        }

        float acc[TOUT];
#pragma unroll
        for (int q = 0; q < TOUT; q++) acc[q] = ieb2;   // folded snake constant

        // y index u = 2*t0 - 5 + j, j=0..25; step i handles j=2i (u odd), j=2i+1 (u even)
#pragma unroll
        for (int i = 0; i < 13; ++i) {
            float yo = UO[0] * rx[i + 3];
            float ye = UE[0] * rx[i + 3];
#pragma unroll
            for (int m = 1; m < 6; ++m) {
                yo = fmaf(UO[m], rx[i + 3 + m], yo);
                ye = fmaf(UE[m], rx[i + 3 + m], ye);
            }
            // snake (3 ops): w = y - ieb2*cos(2*ea*y)   (+ieb2 folded into acc init)
            float co = __cosf(yo * ea2);
            float ce = __cosf(ye * ea2);
            yo = fmaf(nieb2, co, yo);
            ye = fmaf(nieb2, ce, ye);
            // scatter: y[j] feeds acc[q] with tap k = j - 2q in [0,12)
#pragma unroll
            for (int q = 0; q < TOUT; ++q) {
                const int k0 = 2 * i - 2 * q;       // yo (j = 2i)
                if (k0 >= 0 && k0 < 12) acc[q] = fmaf(DD[k0], yo, acc[q]);
                const int k1 = 2 * i + 1 - 2 * q;   // ye (j = 2i+1)
                if (k1 >= 0 && k1 < 12) acc[q] = fmaf(DD[k1], ye, acc[q]);
            }
        }

        *reinterpret_cast<float4*>(orow + t0)     = make_float4(acc[0], acc[1], acc[2], acc[3]);
        *reinterpret_cast<float4*>(orow + t0 + 4) = make_float4(acc[4], acc[5], acc[6], acc[7]);
    } else {
        // Edge path (t0==0 or t0==4088): y-index clamping, same math.
        float acc[TOUT];
#pragma unroll
        for (int q = 0; q < TOUT; q++) acc[q] = ieb2;

#pragma unroll 1
        for (int j = 0; j < 26; ++j) {
            int u = 2 * t0 - 5 + j;
            u = u < 0 ? 0 : (u > T2 - 1 ? T2 - 1 : u);
            const int s   = u >> 1;
            const int idx = s - base;
            float yv;
            if (u & 1) {
                yv = UO[0] * sx[idx - 2];
#pragma unroll
                for (int m = 1; m < 6; ++m) yv = fmaf(UO[m], sx[idx + m - 2], yv);
            } else {
                yv = UE[0] * sx[idx - 3];
#pragma unroll
                for (int m = 1; m < 6; ++m) yv = fmaf(UE[m], sx[idx + m - 3], yv);
            }
            float cc = __cosf(yv * ea2);
            yv = fmaf(nieb2, cc, yv);
#pragma unroll
            for (int q = 0; q < TOUT; ++q) {
                const int k = j - 2 * q;
                if (k >= 0 && k < 12) acc[q] = fmaf(DD[k], yv, acc[q]);
            }
        }
#pragma unroll
        for (int q = 0; q < TOUT; q++) orow[t0 + q] = acc[q];
    }
}

extern "C" void kernel_launch(void* const* d_in, const int* in_sizes, int n_in,
                              void* d_out, int out_size) {
    const float* x     = (const float*)d_in[0];
    const float* alpha = (const float*)d_in[1];
    const float* beta  = (const float*)d_in[2];
    const float* uf    = (const float*)d_in[3];
    const float* df    = (const float*)d_in[4];
    float* out = (float*)d_out;

    dim3 grid(B_N * C_CH * SEGS);   // 32768 blocks
    aa_act_kernel<<<grid, THREADS>>>(x, alpha, beta, uf, df, out);
}